// round 5
// baseline (speedup 1.0000x reference)
#include <cuda_runtime.h>
#include <math.h>

// MultiScaleLMN clockwork RNN — fp32 incremental scan, persistent kernel,
// fence-free release/acquire grid barrier, fused Δ-GEMM + h epilogue.
// T=256, B=64, IN=512, HID=1024, MEM=256, NMOD=8, M=2048
#define T_    256
#define B_    64
#define IN_   512
#define HID_  1024
#define MEM_  256
#define NMOD_ 8
#define M_    2048
#define NBMAX 148
#define NT    256

// ---------------- persistent device scratch ----------------
__device__ __align__(16) float g_P[(size_t)T_ * B_ * HID_];  // x@Wxh precompute
__device__ __align__(16) float g_h[B_ * HID_];               // h_t
__device__ __align__(16) float g_G[B_ * HID_];               // current m@Wmh^T
__device__ __align__(16) float g_U[B_ * M_];                 // current m@Wmm^T
__device__ __align__(16) float g_m[B_ * M_];                 // memory state
__device__ __align__(16) float g_dm[B_ * M_];                // last delta m
__device__ __align__(16) float g_Hpart[16 * B_ * M_];        // h@Whm^T split-K partials
__device__ unsigned g_arrive[NBMAX * 32];                    // barrier flags, 128B apart

// ---------------------------------------------------------------------------
// Fence-free grid barrier. Producer: __syncthreads -> thread0 st.release.gpu.
// Every CTA's warp0 acquire-polls ALL flags (no central release hop).
// Release cumulativity (after bar.sync) publishes the whole CTA's stores;
// acquire-observing every producer's flag + bar.sync imports them CTA-wide.
// Mutable cross-CTA data is read with __ldcg (L2-direct) => no stale L1.
// ---------------------------------------------------------------------------
__device__ __forceinline__ void gsync(unsigned ep) {
    __syncthreads();
    if (threadIdx.x == 0) {
        asm volatile("st.release.gpu.global.u32 [%0], %1;"
                     :: "l"(&g_arrive[blockIdx.x * 32]), "r"(ep) : "memory");
    }
    if (threadIdx.x < 32) {
        for (int s = threadIdx.x; s < (int)gridDim.x; s += 32) {
            unsigned v;
            do {
                asm volatile("ld.acquire.gpu.global.u32 %0, [%1];"
                             : "=r"(v) : "l"(&g_arrive[s * 32]) : "memory");
            } while (v < ep);
        }
    }
    __syncthreads();
}

// ---------------------------------------------------------------------------
// Tile GEMM: out[64 x 32] = A[64 x K] * W[32 x K]^T (overwrite). 256 threads,
// BK=32, microtile 4x2. A via __ldcg (mutable), W via __ldg (weights, L1-hot).
// XOR-swizzled staging (conflict-light STS, vectorized broadcast LDS).
// ---------------------------------------------------------------------------
__device__ __forceinline__ void tile64x32(
    const float* __restrict__ A, int lda,
    const float* __restrict__ W, int ldw, int K,
    float* __restrict__ out, int ldo, float* __restrict__ sm)
{
    float* As = sm;           // 2048 floats
    float* Ws = sm + 2048;    // 1024 floats
    const int tid = threadIdx.x;
    const int rg = tid >> 4;      // r0 = rg*4
    const int cg = tid & 15;      // c0 = cg*2

    float a00 = 0.f, a01 = 0.f, a10 = 0.f, a11 = 0.f;
    float a20 = 0.f, a21 = 0.f, a30 = 0.f, a31 = 0.f;

    for (int kt = 0; kt < K; kt += 32) {
        #pragma unroll
        for (int i = 0; i < 8; i++) {            // A: 64 rows x 32 kk
            int idx = tid + (i << 8);
            int r = idx >> 5, kk = idx & 31;
            As[(kk << 6) + ((((r >> 2) ^ kk) & 15) << 2) + (r & 3)] =
                __ldcg(&A[(size_t)r * lda + kt + kk]);
        }
        #pragma unroll
        for (int i = 0; i < 4; i++) {            // W: 32 cols x 32 kk
            int idx = tid + (i << 8);
            int c = idx >> 5, kk = idx & 31;
            Ws[(kk << 5) + ((((c >> 1) ^ kk) & 15) << 1) + (c & 1)] =
                __ldg(&W[(size_t)c * ldw + kt + kk]);
        }
        __syncthreads();
        #pragma unroll
        for (int kk = 0; kk < 32; kk++) {
            float4 a = *reinterpret_cast<const float4*>(
                &As[(kk << 6) + (((rg ^ kk) & 15) << 2)]);
            float2 w = *reinterpret_cast<const float2*>(
                &Ws[(kk << 5) + (((cg ^ kk) & 15) << 1)]);
            a00 += a.x * w.x; a01 += a.x * w.y;
            a10 += a.y * w.x; a11 += a.y * w.y;
            a20 += a.z * w.x; a21 += a.z * w.y;
            a30 += a.w * w.x; a31 += a.w * w.y;
        }
        __syncthreads();
    }
    const int r0 = rg << 2, c0 = cg << 1;
    *reinterpret_cast<float2*>(&out[(size_t)(r0 + 0) * ldo + c0]) = make_float2(a00, a01);
    *reinterpret_cast<float2*>(&out[(size_t)(r0 + 1) * ldo + c0]) = make_float2(a10, a11);
    *reinterpret_cast<float2*>(&out[(size_t)(r0 + 2) * ldo + c0]) = make_float2(a20, a21);
    *reinterpret_cast<float2*>(&out[(size_t)(r0 + 3) * ldo + c0]) = make_float2(a30, a31);
}

// ---------------------------------------------------------------------------
// Tile GEMM 64x16 with fused state-update epilogue (K unsplit, single writer).
// modes: 0 = G seed (G=acc, h-epilogue), 1 = G update (G+=acc, h-epilogue),
//        2 = U seed (U=acc),             3 = U update (U+=acc)
// h-epilogue: g_h = tanh(P_t + G_new + bh)
// ---------------------------------------------------------------------------
__device__ __forceinline__ void tile64x16(
    const float* __restrict__ A, int lda,
    const float* __restrict__ W, int ldw, int K,
    int mode, int colbase,
    const float* __restrict__ Pt, const float* __restrict__ bh,
    float* __restrict__ sm)
{
    float* As = sm;           // 2048 floats
    float* Ws = sm + 2048;    // 512 floats
    const int tid = threadIdx.x;
    const int rg = tid >> 4;      // r0 = rg*4
    const int c  = tid & 15;

    float a0 = 0.f, a1 = 0.f, a2 = 0.f, a3 = 0.f;

    for (int kt = 0; kt < K; kt += 32) {
        #pragma unroll
        for (int i = 0; i < 8; i++) {            // A: 64 rows x 32 kk
            int idx = tid + (i << 8);
            int r = idx >> 5, kk = idx & 31;
            As[(kk << 6) + ((((r >> 2) ^ kk) & 15) << 2) + (r & 3)] =
                __ldcg(&A[(size_t)r * lda + kt + kk]);
        }
        #pragma unroll
        for (int i = 0; i < 2; i++) {            // W: 16 cols x 32 kk
            int idx = tid + (i << 8);
            int cc = idx >> 5, kk = idx & 31;
            Ws[(kk << 4) + ((cc ^ kk) & 15)] =
                __ldg(&W[(size_t)cc * ldw + kt + kk]);
        }
        __syncthreads();
        #pragma unroll
        for (int kk = 0; kk < 32; kk++) {
            float4 a = *reinterpret_cast<const float4*>(
                &As[(kk << 6) + (((rg ^ kk) & 15) << 2)]);
            float w = Ws[(kk << 4) + ((c ^ kk) & 15)];
            a0 += a.x * w; a1 += a.y * w; a2 += a.z * w; a3 += a.w * w;
        }
        __syncthreads();
    }
    const int r0 = rg << 2;
    const int col = colbase + c;
    float acc[4] = {a0, a1, a2, a3};
    if (mode <= 1) {
        float bb = __ldg(&bh[col]);
        #pragma unroll
        for (int i = 0; i < 4; i++) {
            size_t idx = (size_t)(r0 + i) * HID_ + col;
            float g = acc[i];
            if (mode == 1) g += __ldcg(&g_G[idx]);
            g_G[idx] = g;
            g_h[idx] = tanhf(__ldg(&Pt[idx]) + g + bb);
        }
    } else {
        #pragma unroll
        for (int i = 0; i < 4; i++) {
            size_t idx = (size_t)(r0 + i) * M_ + col;
            float u = acc[i];
            if (mode == 3) u += __ldcg(&g_U[idx]);
            g_U[idx] = u;
        }
    }
}

// ---------------------------------------------------------------------------
// Fused phase D+A: G += dm@Wmh^T then h=tanh(P_{tnext}+G+bh); U += dm@Wmm^T.
// kp = #active modules of the dm being applied. seed: dmsrc=m_prev, kp=8.
// Tiles: 64 G-coltiles (K=kp*256) + 16*kp U-tiles (K=(kp-bj)*256).
// ---------------------------------------------------------------------------
__device__ __forceinline__ void phaseDA(
    const float* __restrict__ dmsrc, int kp, int seed, int tnext,
    const float* __restrict__ Wmh, const float* __restrict__ Wmm,
    const float* __restrict__ bh, float* __restrict__ sm, int bid, int gsz)
{
    const float* Pt = g_P + (size_t)tnext * B_ * HID_;
    const int ntiles = 64 + 16 * kp;
    for (int tt = bid; tt < ntiles; tt += gsz) {
        if (tt < 64) {
            int cb = tt * 16;
            tile64x16(dmsrc, M_, Wmh + (size_t)cb * M_, M_, kp * MEM_,
                      seed ? 0 : 1, cb, Pt, bh, sm);
        } else {
            int u = tt - 64, bj = u >> 4, ct = u & 15;
            int K = (kp - bj) * MEM_;
            tile64x16(dmsrc + bj * MEM_, M_,
                      Wmm + (size_t)(bj * MEM_ + ct * 16) * M_ + bj * MEM_, M_, K,
                      seed ? 2 : 3, bj * MEM_ + ct * 16, Pt, bh, sm);
        }
    }
}

// ---------------------------------------------------------------------------
// Precompute P[16384,1024] = x[16384,512] @ Wxh[512,1024]  (parallel node)
// ---------------------------------------------------------------------------
__global__ __launch_bounds__(256) void gemm_P(
    const float* __restrict__ x, const float* __restrict__ Wxh)
{
    __shared__ __align__(16) float Xs[16][132];
    __shared__ __align__(16) float Ws[16][132];
    const int tid  = threadIdx.x;
    const int row0 = blockIdx.x * 128;
    const int col0 = blockIdx.y * 128;
    const int c0 = (tid & 15) * 8;
    const int r0 = (tid >> 4) * 8;

    float acc[8][8];
    #pragma unroll
    for (int r = 0; r < 8; r++)
        #pragma unroll
        for (int c = 0; c < 8; c++) acc[r][c] = 0.f;

    for (int kt = 0; kt < IN_; kt += 16) {
        #pragma unroll
        for (int i = tid; i < 128 * 16; i += 256) {
            int r = i >> 4, kk = i & 15;
            Xs[kk][r] = x[(size_t)(row0 + r) * IN_ + kt + kk];
        }
        #pragma unroll
        for (int i = tid; i < 128 * 16; i += 256) {
            int kk = i >> 7, c = i & 127;
            Ws[kk][c] = Wxh[(size_t)(kt + kk) * HID_ + col0 + c];
        }
        __syncthreads();
        #pragma unroll
        for (int kk = 0; kk < 16; kk++) {
            float4 x0 = *reinterpret_cast<const float4*>(&Xs[kk][r0]);
            float4 x1 = *reinterpret_cast<const float4*>(&Xs[kk][r0 + 4]);
            float4 w0 = *reinterpret_cast<const float4*>(&Ws[kk][c0]);
            float4 w1 = *reinterpret_cast<const float4*>(&Ws[kk][c0 + 4]);
            float av[8] = {x0.x, x0.y, x0.z, x0.w, x1.x, x1.y, x1.z, x1.w};
            float wv[8] = {w0.x, w0.y, w0.z, w0.w, w1.x, w1.y, w1.z, w1.w};
            #pragma unroll
            for (int r = 0; r < 8; r++)
                #pragma unroll
                for (int c = 0; c < 8; c++) acc[r][c] += av[r] * wv[c];
        }
        __syncthreads();
    }
    #pragma unroll
    for (int r = 0; r < 8; r++) {
        float4* o0 = reinterpret_cast<float4*>(&g_P[(size_t)(row0 + r0 + r) * HID_ + col0 + c0]);
        *o0       = make_float4(acc[r][0], acc[r][1], acc[r][2], acc[r][3]);
        *(o0 + 1) = make_float4(acc[r][4], acc[r][5], acc[r][6], acc[r][7]);
    }
}

// ---------------------------------------------------------------------------
// Init: m = m_prev, barrier flags = 0  (re-run on every graph replay)
// ---------------------------------------------------------------------------
__global__ void k_init(const float* __restrict__ m_prev) {
    if (blockIdx.x == 0) {
        for (int j = threadIdx.x; j < NBMAX * 32; j += 256) g_arrive[j] = 0;
    }
    int idx = blockIdx.x * 256 + threadIdx.x;   // 32768 float4 slots of m
    int e = idx * 4;
    *reinterpret_cast<float4*>(&g_m[e]) = *reinterpret_cast<const float4*>(&m_prev[e]);
}

// ---------------------------------------------------------------------------
// Persistent scan: seed G/U (+h_0) from m_prev, then per step t:
//   B: Hpart[s] = h@Whm^T over active cols (ns split-K slices)
//   C: m_new = U + bm + sum_s Hpart  on active cols; dm; write out
//   DA: G += dm@Wmh^T (h_{t+1} epilogue); U += dm@Wmm^T
// 3 grid barriers per step (768 total), no gpu-scope fences.
// ---------------------------------------------------------------------------
__global__ __launch_bounds__(NT, 1) void k_scan(
    const float* __restrict__ m_prev,
    const float* __restrict__ Whm, const float* __restrict__ Wmm,
    const float* __restrict__ Wmh,
    const float* __restrict__ bm,  const float* __restrict__ bh,
    float* __restrict__ out, int full, int tail)
{
    __shared__ __align__(16) float sm[3072];
    const int bid = blockIdx.x;
    const int gsz = gridDim.x;
    const int tid = threadIdx.x;
    unsigned ep = 0;

    // ---- phase 0: seed G/U from m_prev, compute h_0 ----
    phaseDA(m_prev, NMOD_, 1, 0, Wmh, Wmm, bh, sm, bid, gsz);
    gsync(++ep);

    for (int t = 0; t < T_; t++) {
        int k = 0;
        while (k < NMOD_ && (t & ((1 << k) - 1)) == 0) k++;
        const int ns = (k == 1) ? 16 : 8;       // split-K slices for Hpart
        const int sh = (k == 1) ? 4 : 3;
        const int ksl = HID_ / ns;              // 64 or 128

        // ---- phase B: Hpart slices over active columns ----
        {
            int nB = (8 * k) << sh;             // coltiles * ns
            for (int tt = bid; tt < nB; tt += gsz) {
                int s = tt & (ns - 1), ct = tt >> sh;
                int j0 = ct * 32;
                tile64x32(g_h + s * ksl, HID_,
                          Whm + (size_t)j0 * HID_ + s * ksl, HID_, ksl,
                          g_Hpart + (size_t)s * B_ * M_ + j0, M_, sm);
            }
        }
        gsync(++ep);

        // ---- phase C: finalize m_t, dm, write out ----
        {
            float* outp = full ? out + (size_t)t * B_ * M_
                               : (t == T_ - 1 ? out : (float*)0);
            for (int i = bid * NT + tid; i < 32768; i += gsz * NT) {
                int e = i * 4;
                int j = e & (M_ - 1);
                float4 res;
                if (j < k * MEM_) {
                    float4 u = __ldcg(reinterpret_cast<const float4*>(&g_U[e]));
                    float4 bb = *reinterpret_cast<const float4*>(&bm[j]);
                    float4 mn = make_float4(u.x + bb.x, u.y + bb.y, u.z + bb.z, u.w + bb.w);
                    for (int s = 0; s < ns; s++) {
                        float4 hp = __ldcg(reinterpret_cast<const float4*>(
                            &g_Hpart[(size_t)s * B_ * M_ + e]));
                        mn.x += hp.x; mn.y += hp.y; mn.z += hp.z; mn.w += hp.w;
                    }
                    float4 old = __ldcg(reinterpret_cast<const float4*>(&g_m[e]));
                    *reinterpret_cast<float4*>(&g_dm[e]) =
                        make_float4(mn.x - old.x, mn.y - old.y, mn.z - old.z, mn.w - old.w);
                    *reinterpret_cast<float4*>(&g_m[e]) = mn;
                    res = mn;
                } else {
                    res = __ldcg(reinterpret_cast<const float4*>(&g_m[e]));
                }
                if (outp) *reinterpret_cast<float4*>(&outp[e]) = res;
                if (tail && t == T_ - 1)
                    *reinterpret_cast<float4*>(&out[(size_t)T_ * B_ * M_ + e]) = res;
            }
        }
        gsync(++ep);

        // ---- phase DA: apply dm to G (h_{t+1} epilogue) and U ----
        if (t < T_ - 1) {
            phaseDA(g_dm, k, 0, t + 1, Wmh, Wmm, bh, sm, bid, gsz);
            gsync(++ep);
        }
    }
}

// ---------------------------------------------------------------------------
extern "C" void kernel_launch(void* const* d_in, const int* in_sizes, int n_in,
                              void* d_out, int out_size) {
    const float* x      = (const float*)d_in[0];
    const float* m_prev = (const float*)d_in[1];
    const float* Wxh    = (const float*)d_in[2];
    const float* Whm    = (const float*)d_in[3];
    const float* Wmm    = (const float*)d_in[4];
    const float* Wmh    = (const float*)d_in[5];
    const float* bm     = (const float*)d_in[6];
    const float* bh     = (const float*)d_in[7];
    float* out = (float*)d_out;

    const size_t outs_elems = (size_t)T_ * B_ * M_;
    const int full = ((size_t)out_size >= outs_elems) ? 1 : 0;
    const int tail = ((size_t)out_size >= outs_elems + (size_t)B_ * M_) ? 1 : 0;

    int dev = 0, sms = NBMAX;
    cudaGetDevice(&dev);
    if (cudaDeviceGetAttribute(&sms, cudaDevAttrMultiProcessorCount, dev) != cudaSuccess)
        sms = NBMAX;
    int grid = sms < NBMAX ? sms : NBMAX;

    gemm_P<<<dim3(128, 8), 256>>>(x, Wxh);
    k_init<<<128, 256>>>(m_prev);
    k_scan<<<grid, NT>>>(m_prev, Whm, Wmm, Wmh, bm, bh, out, full, tail);
}